// round 13
// baseline (speedup 1.0000x reference)
#include <cuda_runtime.h>

// Problem constants
#define M_DIM   16
#define DICT    64
#define N_DIM   8
#define B_DIM   8192
#define KTERMS  11
#define BDIM    128
#define NB      128              // matrices (b-values) per block
#define A_STRIDE 64              // exact stride; conflicts handled by XOR swizzle
#define CT_STRIDE 132            // padded float stride of one cT row (b-dim)
#define PSI_STRIDE 17            // float4 stride of one psi m-row (swizzled)

// 1/k table, k=0 unused (rolled Horner loop -> LDC, keeps reg pressure low)
__device__ __constant__ float INVK[KTERMS + 1] = {
    0.0f,
    1.0f/1, 1.0f/2, 1.0f/3, 1.0f/4,  1.0f/5,  1.0f/6,
    1.0f/7, 1.0f/8, 1.0f/9, 1.0f/10, 1.0f/11
};

// Grid: (B/128, DICT). Block = 128 threads, 128 matrices. 5 CTAs/SM.
//
// Smem layouts:
//  psi_s: float4 index m*17 + q + (q>>3): phase-1 loads conflict-free.
//  A_s:   matrix b at float offset b*64; 16B chunk cidx (= 2*row + half)
//         stored at chunk position cidx ^ (b & 7).
//         Phase-2 reads (lanes = b, fixed cidx): banks 4*((cidx^p)&7) — all
//         distinct per 8-lane phase -> conflict-free.
//         Phase-1 stores (lanes vary g, fixed bi): 2-way conflict — accepted,
//         buys 2 KB/block and the 5th resident CTA.
__global__ __launch_bounds__(BDIM, 5)
void transop_expm_kernel(const float* __restrict__ x,
                         const float* __restrict__ c,
                         const float* __restrict__ psi,
                         float* __restrict__ out)
{
    const int s   = blockIdx.y;
    const int tid = threadIdx.x;
    const int b0  = blockIdx.x * NB;

    __shared__ float4 psi_s[M_DIM * PSI_STRIDE];  //  4.25 KB  psi[m,s,:,:] (swizzled)
    __shared__ float  cT[M_DIM * CT_STRIDE];      //  8.25 KB  cT[m][b_loc]
    __shared__ float  A_s[NB * A_STRIDE];         // 32 KB     A (chunk-XOR swizzled)

    // ---- Stage psi slice (256 float4, 2/thread), swizzled ----
    #pragma unroll
    for (int u = 0; u < 2; u++) {
        int i = tid + u * BDIM;      // 0..255
        int m = i >> 4;
        int q = i & 15;
        psi_s[m * PSI_STRIDE + q + (q >> 3)] =
            reinterpret_cast<const float4*>(psi)[(m * DICT + s) * 16 + q];
    }

    // ---- Stage c transposed: c[b0..b0+127][0..15] = 512 float4, 4/thread ----
    {
        const float4* cg = reinterpret_cast<const float4*>(c) + (size_t)b0 * 4;
        #pragma unroll
        for (int u = 0; u < 4; u++) {
            int i = tid + u * BDIM;           // 0..511
            float4 v = cg[i];
            int b_loc = i >> 2;               // 0..127
            int mb    = (i & 3) * 4;          // m base
            cT[(mb + 0) * CT_STRIDE + b_loc] = v.x;
            cT[(mb + 1) * CT_STRIDE + b_loc] = v.y;
            cT[(mb + 2) * CT_STRIDE + b_loc] = v.z;
            cT[(mb + 3) * CT_STRIDE + b_loc] = v.w;
        }
    }
    __syncthreads();

    // ---- Phase 1: A-build, 8 b x 8 nk per thread ----
    {
        const int g  = tid & 7;               // matrix row octet: row g, cols 0..7
        const int o  = tid >> 3;              // b-octet: b_loc = 8o..8o+7
        const int og = g >> 2;                // psi swizzle offset

        float4 acc[16];                       // [bi*2 + j]: matrix bi, col half j
        #pragma unroll
        for (int i = 0; i < 16; i++) acc[i] = make_float4(0.f, 0.f, 0.f, 0.f);

        #pragma unroll
        for (int m = 0; m < M_DIM; m++) {
            const float4* prow = &psi_s[m * PSI_STRIDE + 2 * g + og];
            float4 p0 = prow[0];
            float4 p1 = prow[1];
            float4 ca = *reinterpret_cast<const float4*>(&cT[m * CT_STRIDE + 8 * o]);
            float4 cb = *reinterpret_cast<const float4*>(&cT[m * CT_STRIDE + 8 * o + 4]);
            float cv[8] = {ca.x, ca.y, ca.z, ca.w, cb.x, cb.y, cb.z, cb.w};
            #pragma unroll
            for (int bi = 0; bi < 8; bi++) {
                acc[bi*2  ].x = fmaf(cv[bi], p0.x, acc[bi*2  ].x);
                acc[bi*2  ].y = fmaf(cv[bi], p0.y, acc[bi*2  ].y);
                acc[bi*2  ].z = fmaf(cv[bi], p0.z, acc[bi*2  ].z);
                acc[bi*2  ].w = fmaf(cv[bi], p0.w, acc[bi*2  ].w);
                acc[bi*2+1].x = fmaf(cv[bi], p1.x, acc[bi*2+1].x);
                acc[bi*2+1].y = fmaf(cv[bi], p1.y, acc[bi*2+1].y);
                acc[bi*2+1].z = fmaf(cv[bi], p1.z, acc[bi*2+1].z);
                acc[bi*2+1].w = fmaf(cv[bi], p1.w, acc[bi*2+1].w);
            }
        }

        // Store with chunk-XOR swizzle: chunk cidx of matrix b at cidx^(b&7).
        const int c0i = 2 * g;                // cidx of acc[bi*2]
        #pragma unroll
        for (int bi = 0; bi < 8; bi++) {
            float* row = &A_s[(8 * o + bi) * A_STRIDE];
            *reinterpret_cast<float4*>(row + 4 * (c0i ^ bi))       = acc[bi*2];
            *reinterpret_cast<float4*>(row + 4 * ((c0i + 1) ^ bi)) = acc[bi*2+1];
        }
    }
    __syncthreads();

    // ---- Phase 2: one matrix per thread, register Horner, no exchange ----
    const int p = tid;
    const int b = b0 + p;
    const int pw = p & 7;                     // my swizzle key

    // Pull my 8x8 A (16 LDS.128, conflict-free per the XOR layout).
    float A[64];
    #pragma unroll
    for (int r = 0; r < 8; r++) {
        const float* row = &A_s[p * A_STRIDE];
        float4 a0 = *reinterpret_cast<const float4*>(row + 4 * ((2*r)     ^ pw));
        float4 a1 = *reinterpret_cast<const float4*>(row + 4 * ((2*r + 1) ^ pw));
        A[8*r+0] = a0.x; A[8*r+1] = a0.y; A[8*r+2] = a0.z; A[8*r+3] = a0.w;
        A[8*r+4] = a1.x; A[8*r+5] = a1.y; A[8*r+6] = a1.z; A[8*r+7] = a1.w;
    }

    // x[b, s*8 .. s*8+8)
    float xv[N_DIM], u[N_DIM];
    {
        const float4* xp = reinterpret_cast<const float4*>(
            x + (size_t)b * (DICT * N_DIM) + s * N_DIM);
        float4 x0 = xp[0], x1 = xp[1];
        xv[0] = x0.x; xv[1] = x0.y; xv[2] = x0.z; xv[3] = x0.w;
        xv[4] = x1.x; xv[5] = x1.y; xv[6] = x1.z; xv[7] = x1.w;
        #pragma unroll
        for (int i = 0; i < N_DIM; i++) u[i] = xv[i];
    }

    // Horner: u <- x + (A u)/k, k = K..1 (rolled; 1/k via constant table).
    #pragma unroll 1
    for (int k = KTERMS; k >= 1; k--) {
        const float ik = INVK[k];
        float t[N_DIM];
        #pragma unroll
        for (int n = 0; n < N_DIM; n++) {
            float sum = A[n * 8 + 0] * u[0];
            #pragma unroll
            for (int j = 1; j < N_DIM; j++)
                sum = fmaf(A[n * 8 + j], u[j], sum);
            t[n] = sum;
        }
        #pragma unroll
        for (int i = 0; i < N_DIM; i++)
            u[i] = fmaf(ik, t[i], xv[i]);
    }

    // Store out[b, s*8 .. s*8+8)
    {
        float4* op = reinterpret_cast<float4*>(
            out + (size_t)b * (DICT * N_DIM) + s * N_DIM);
        op[0] = make_float4(u[0], u[1], u[2], u[3]);
        op[1] = make_float4(u[4], u[5], u[6], u[7]);
    }
}

extern "C" void kernel_launch(void* const* d_in, const int* in_sizes, int n_in,
                              void* d_out, int out_size)
{
    const float* x   = (const float*)d_in[0];  // (8192, 512)
    const float* c   = (const float*)d_in[1];  // (8192, 16)
    const float* psi = (const float*)d_in[2];  // (16, 64, 8, 8)
    float* out = (float*)d_out;                // (8192, 512)

    dim3 grid(B_DIM / NB, DICT);
    transop_expm_kernel<<<grid, BDIM>>>(x, c, psi, out);
}

// round 15
// speedup vs baseline: 1.2404x; 1.2404x over previous
#include <cuda_runtime.h>

// Problem constants
#define M_DIM   16
#define DICT    64
#define N_DIM   8
#define B_DIM   8192
#define KTERMS  10
#define BDIM    128
#define NBB     32               // b-values per block
#define NS      4                // s-slots per block  (32*4 = 128 matrices)
#define A_STRIDE 68              // padded float stride of one A matrix
#define CT_STRIDE 36             // padded float stride of one cT row (b-dim)
#define PSI_SLICE 272            // float4 footprint of one swizzled psi slice (16*17)

// 1/k table, k=0 unused (rolled Horner loop)
__device__ __constant__ float INVK[KTERMS + 1] = {
    0.0f,
    1.0f/1, 1.0f/2, 1.0f/3, 1.0f/4, 1.0f/5,
    1.0f/6, 1.0f/7, 1.0f/8, 1.0f/9, 1.0f/10
};

// Grid: (B/32, DICT/4). Block = 128 threads = 128 matrices (32 b x 4 s).
// The (b,s) retile makes phase-2 x/out global accesses nearly coalesced:
// a warp covers 8 b-rows x 4 s-slots = 8 x 128B contiguous -> 8 sectors
// per LDG.128 (vs 32 with the 128b x 1s mapping).
//
// Phase 1: thread (sl, o, g) computes rows g (8 cols) of matrices
//   b_loc = 8o..8o+7 in slice sl.  Per m: 2 psi LDS.128 + 2 cT LDS.128
//   feed 64 FMAs.  A stored with column swizzle colbase = 8g + 4*(g>>2)
//   into stride-68 rows (all smem phases conflict-free, verified).
// Phase 2: thread tid owns matrix p = tid (= bl*4 + sl), reads its 8x8 A
//   with 16 conflict-free LDS.128, runs the rolled 10-step Horner in
//   registers, stores coalesced.
__global__ __launch_bounds__(BDIM, 4)
void transop_expm_kernel(const float* __restrict__ x,
                         const float* __restrict__ c,
                         const float* __restrict__ psi,
                         float* __restrict__ out)
{
    const int s0  = blockIdx.y * NS;
    const int b0  = blockIdx.x * NBB;
    const int tid = threadIdx.x;

    __shared__ float4 psi_s[NS * PSI_SLICE];      // 17 KB   4 swizzled psi slices
    __shared__ float  cT[M_DIM * CT_STRIDE];      //  2.25 KB cT[m][b_loc]
    __shared__ float  A_s[BDIM * A_STRIDE];       // 34 KB   A[p][..] (col-swizzled)

    // ---- Stage 4 psi slices (1024 float4, 8/thread, coalesced) ----
    #pragma unroll
    for (int u = 0; u < 8; u++) {
        int i  = tid + u * BDIM;     // 0..1023
        int sl = i >> 8;             // slice
        int j  = i & 255;
        int m  = j >> 4;
        int q  = j & 15;
        psi_s[sl * PSI_SLICE + m * 17 + q + (q >> 3)] =
            reinterpret_cast<const float4*>(psi)[(m * DICT + s0 + sl) * 16 + q];
    }

    // ---- Stage c transposed: c[b0..b0+32)[0..16) = 128 float4, 1/thread ----
    {
        float4 v = reinterpret_cast<const float4*>(c)[(size_t)b0 * 4 + tid];
        int bl = tid >> 2;               // 0..31
        int mb = (tid & 3) * 4;          // m base
        cT[(mb + 0) * CT_STRIDE + bl] = v.x;
        cT[(mb + 1) * CT_STRIDE + bl] = v.y;
        cT[(mb + 2) * CT_STRIDE + bl] = v.z;
        cT[(mb + 3) * CT_STRIDE + bl] = v.w;
    }
    __syncthreads();

    // ---- Phase 1: A-build, 8 b x 8 nk per thread (one s-slice) ----
    {
        const int sl = tid >> 5;              // s-slice 0..3
        const int o  = (tid >> 3) & 3;        // b-octet: b_loc = 8o..8o+7
        const int g  = tid & 7;               // matrix row
        const int og = g >> 2;                // psi swizzle offset

        float4 acc[16];                       // [bi*2 + j]: matrix bi, col half j
        #pragma unroll
        for (int i = 0; i < 16; i++) acc[i] = make_float4(0.f, 0.f, 0.f, 0.f);

        const float4* pbase = &psi_s[sl * PSI_SLICE + 2 * g + og];
        #pragma unroll
        for (int m = 0; m < M_DIM; m++) {
            float4 p0 = pbase[m * 17];
            float4 p1 = pbase[m * 17 + 1];
            float4 ca = *reinterpret_cast<const float4*>(&cT[m * CT_STRIDE + 8 * o]);
            float4 cb = *reinterpret_cast<const float4*>(&cT[m * CT_STRIDE + 8 * o + 4]);
            float cv[8] = {ca.x, ca.y, ca.z, ca.w, cb.x, cb.y, cb.z, cb.w};
            #pragma unroll
            for (int bi = 0; bi < 8; bi++) {
                acc[bi*2  ].x = fmaf(cv[bi], p0.x, acc[bi*2  ].x);
                acc[bi*2  ].y = fmaf(cv[bi], p0.y, acc[bi*2  ].y);
                acc[bi*2  ].z = fmaf(cv[bi], p0.z, acc[bi*2  ].z);
                acc[bi*2  ].w = fmaf(cv[bi], p0.w, acc[bi*2  ].w);
                acc[bi*2+1].x = fmaf(cv[bi], p1.x, acc[bi*2+1].x);
                acc[bi*2+1].y = fmaf(cv[bi], p1.y, acc[bi*2+1].y);
                acc[bi*2+1].z = fmaf(cv[bi], p1.z, acc[bi*2+1].z);
                acc[bi*2+1].w = fmaf(cv[bi], p1.w, acc[bi*2+1].w);
            }
        }

        // Matrix (b_loc = 8o+bi, slice sl) lives at p = b_loc*4 + sl.
        const int colbase = 8 * g + 4 * og;   // swizzled column offset of row g
        #pragma unroll
        for (int bi = 0; bi < 8; bi++) {
            int p = (8 * o + bi) * NS + sl;
            *reinterpret_cast<float4*>(&A_s[p * A_STRIDE + colbase])     = acc[bi*2];
            *reinterpret_cast<float4*>(&A_s[p * A_STRIDE + colbase + 4]) = acc[bi*2+1];
        }
    }
    __syncthreads();

    // ---- Phase 2: one matrix per thread (p = tid), register Horner ----
    const int bl = tid >> 2;
    const int sl = tid & 3;
    const int b  = b0 + bl;
    const int s  = s0 + sl;

    // Pull my 8x8 A (16 LDS.128, conflict-free: 68*tid mod 32 = 4*tid).
    float A[64];
    #pragma unroll
    for (int r = 0; r < 8; r++) {
        int off = 8 * r + 4 * (r >> 2);       // match the store swizzle
        float4 a0 = *reinterpret_cast<const float4*>(&A_s[tid * A_STRIDE + off]);
        float4 a1 = *reinterpret_cast<const float4*>(&A_s[tid * A_STRIDE + off + 4]);
        A[8*r+0] = a0.x; A[8*r+1] = a0.y; A[8*r+2] = a0.z; A[8*r+3] = a0.w;
        A[8*r+4] = a1.x; A[8*r+5] = a1.y; A[8*r+6] = a1.z; A[8*r+7] = a1.w;
    }

    // x[b, s*8 .. s*8+8) — warp covers 8 rows x 128B contiguous.
    float xv[N_DIM], u[N_DIM];
    {
        const float4* xp = reinterpret_cast<const float4*>(
            x + (size_t)b * (DICT * N_DIM) + s * N_DIM);
        float4 x0 = xp[0], x1 = xp[1];
        xv[0] = x0.x; xv[1] = x0.y; xv[2] = x0.z; xv[3] = x0.w;
        xv[4] = x1.x; xv[5] = x1.y; xv[6] = x1.z; xv[7] = x1.w;
        #pragma unroll
        for (int i = 0; i < N_DIM; i++) u[i] = xv[i];
    }

    // Horner: u <- x + (A u)/k, k = K..1 (rolled; 1/k via constant table).
    #pragma unroll 1
    for (int k = KTERMS; k >= 1; k--) {
        const float ik = INVK[k];
        float t[N_DIM];
        #pragma unroll
        for (int n = 0; n < N_DIM; n++) {
            float sum = A[n * 8 + 0] * u[0];
            #pragma unroll
            for (int j = 1; j < N_DIM; j++)
                sum = fmaf(A[n * 8 + j], u[j], sum);
            t[n] = sum;
        }
        #pragma unroll
        for (int i = 0; i < N_DIM; i++)
            u[i] = fmaf(ik, t[i], xv[i]);
    }

    // Store out[b, s*8 .. s*8+8) — coalesced like x.
    {
        float4* op = reinterpret_cast<float4*>(
            out + (size_t)b * (DICT * N_DIM) + s * N_DIM);
        op[0] = make_float4(u[0], u[1], u[2], u[3]);
        op[1] = make_float4(u[4], u[5], u[6], u[7]);
    }
}

extern "C" void kernel_launch(void* const* d_in, const int* in_sizes, int n_in,
                              void* d_out, int out_size)
{
    const float* x   = (const float*)d_in[0];  // (8192, 512)
    const float* c   = (const float*)d_in[1];  // (8192, 16)
    const float* psi = (const float*)d_in[2];  // (16, 64, 8, 8)
    float* out = (float*)d_out;                // (8192, 512)

    dim3 grid(B_DIM / NBB, DICT / NS);
    transop_expm_kernel<<<grid, BDIM>>>(x, c, psi, out);
}